// round 12
// baseline (speedup 1.0000x reference)
#include <cuda_runtime.h>
#include <cuda_fp16.h>
#include <math.h>
#include <stdint.h>

#define B_   8
#define N_   8192
#define C_   256
#define H_   128
#define W_   128
#define NH_  8
#define HW_  (H_ * W_)
#define M_   (B_ * N_)      // 65536
#define P96  96
#define KS   512            // stored K (hi | lo), both GEMMs

// ---- scratch (static device allocations; no cudaMalloc anywhere) ----
__device__ __half g_valth[(size_t)B_ * NH_ * HW_ * 32];     // (B,Hh,HW,D) fp16, 67MB
__device__ float g_params[(size_t)M_ * P96];                // [off(64) | attn(32)]
__device__ __half g_qs[(size_t)M_ * KS];                    // query splits [M][512]
__device__ __half g_as[(size_t)M_ * KS];                    // agg splits   [M][512]
__device__ __half g_wc[128 * KS];                           // wcat^T splits (pad rows 96-127)
__device__ __half g_wo[C_ * KS];                            // W_out^T splits
__device__ float g_bcat[P96];

// ============================ PTX helpers ==================================
__device__ __forceinline__ uint32_t smem_u32(const void* p) {
    uint32_t a;
    asm("{ .reg .u64 t; cvta.to.shared.u64 t, %1; cvt.u32.u64 %0, t; }"
        : "=r"(a) : "l"(p));
    return a;
}
__device__ __forceinline__ void cp16(uint32_t dst, const void* src) {
    asm volatile("cp.async.cg.shared.global [%0], [%1], 16;" :: "r"(dst), "l"(src));
}
#define CP_COMMIT() asm volatile("cp.async.commit_group;" ::: "memory")
#define CP_WAIT(n)  asm volatile("cp.async.wait_group %0;" :: "n"(n) : "memory")

__device__ __forceinline__ void ldsm4(uint32_t* r, uint32_t addr) {
    asm volatile("ldmatrix.sync.aligned.m8n8.x4.shared.b16 {%0,%1,%2,%3}, [%4];"
                 : "=r"(r[0]), "=r"(r[1]), "=r"(r[2]), "=r"(r[3]) : "r"(addr));
}
__device__ __forceinline__ void mma_f16(float* d, const uint32_t* a, const uint32_t* b) {
    asm volatile(
        "mma.sync.aligned.m16n8k16.row.col.f32.f16.f16.f32 "
        "{%0,%1,%2,%3}, {%4,%5,%6,%7}, {%8,%9}, {%0,%1,%2,%3};"
        : "+f"(d[0]), "+f"(d[1]), "+f"(d[2]), "+f"(d[3])
        : "r"(a[0]), "r"(a[1]), "r"(a[2]), "r"(a[3]), "r"(b[0]), "r"(b[1]));
}
__device__ __forceinline__ uint32_t swz(uint32_t off) { return off ^ ((off >> 3) & 0x70); }

// ============================ fp16 2-way split =============================
__device__ __forceinline__ void split2h(float v, __half& h, __half& l) {
    h = __float2half(v);
    l = __float2half(v - __half2float(h));
}

// query -> [M][512] (hi | lo)
__global__ void split_query_kernel(const float* __restrict__ q) {
    size_t i = (size_t)(blockIdx.x * blockDim.x + threadIdx.x) * 4;
    float4 v = *(const float4*)&q[i];
    size_t row = i >> 8;
    int col = (int)(i & 255);
    __half h[4], l[4];
    split2h(v.x, h[0], l[0]); split2h(v.y, h[1], l[1]);
    split2h(v.z, h[2], l[2]); split2h(v.w, h[3], l[3]);
    __half* base = g_qs + row * KS + col;
    *(__half2*)(base)       = __half2(h[0], h[1]);
    *(__half2*)(base + 2)   = __half2(h[2], h[3]);
    *(__half2*)(base + 256) = __half2(l[0], l[1]);
    *(__half2*)(base + 258) = __half2(l[2], l[3]);
}

// wcat^T -> [128][512] padded with zero rows 96..127
__global__ void prep_wcat_kernel(const float* __restrict__ W_off,
                                 const float* __restrict__ b_off,
                                 const float* __restrict__ W_attn,
                                 const float* __restrict__ b_attn) {
    int id = blockIdx.x * blockDim.x + threadIdx.x;   // 128*256
    int j = id >> 8, k = id & 255;
    float v = 0.f;
    if (j < 64)       v = W_off[k * 64 + j];
    else if (j < 96)  v = W_attn[k * 32 + (j - 64)];
    __half h, l;
    split2h(v, h, l);
    g_wc[j * KS + k] = h; g_wc[j * KS + 256 + k] = l;
    if (id < P96) g_bcat[id] = (id < 64) ? b_off[id] : b_attn[id - 64];
}

// W_out^T -> [256][512]
__global__ void prep_wout_kernel(const float* __restrict__ W_out) {
    int id = blockIdx.x * blockDim.x + threadIdx.x;   // 256*256
    int n = id >> 8, k = id & 255;
    __half h, l;
    split2h(W_out[k * C_ + n], h, l);
    g_wo[n * KS + k] = h; g_wo[n * KS + 256 + k] = l;
}

// ---------------------------------------------------------------------------
// Transpose v4: (B, Hh*D, H*W) fp32 -> (B, Hh, H*W, D) fp16.
// ---------------------------------------------------------------------------
__global__ void transpose_val_kernel(const float* __restrict__ val) {
    __shared__ float4 t4[64][8];
    int bh = blockIdx.y;
    int p0 = blockIdx.x * 64;
    int tid = threadIdx.x;
    int dl = tid >> 6;         // 0..3
    int pl = tid & 63;         // 0..63
    const float* src = val + ((size_t)bh * 32) * HW_ + p0 + pl;
#pragma unroll
    for (int i = 0; i < 2; i++) {
        int dq = dl * 2 + i;   // 0..7
        float4 v;
        v.x = src[(size_t)(dq * 4 + 0) * HW_];
        v.y = src[(size_t)(dq * 4 + 1) * HW_];
        v.z = src[(size_t)(dq * 4 + 2) * HW_];
        v.w = src[(size_t)(dq * 4 + 3) * HW_];
        t4[pl][dq ^ (pl & 7)] = v;
    }
    __syncthreads();
    int c  = tid & 7;          // output d-quad
    int pw = tid >> 3;         // 0..31
    __half* dst = g_valth + (size_t)bh * HW_ * 32 + (size_t)p0 * 32;
#pragma unroll
    for (int i = 0; i < 2; i++) {
        int p = pw + i * 32;
        float4 v = t4[p][c ^ (p & 7)];
        __half2 h01 = __floats2half2_rn(v.x, v.y);
        __half2 h23 = __floats2half2_rn(v.z, v.w);
        uint2 u;
        u.x = *reinterpret_cast<uint32_t*>(&h01);
        u.y = *reinterpret_cast<uint32_t*>(&h23);
        *(uint2*)&dst[(size_t)p * 32 + c * 4] = u;
    }
}

// ===========================================================================
// fp16 mma.sync GEMM, split-compensated.
// MODE 0 (GEMM-1): 12 chunks, A sections {hi,hi,lo}, B {hi,lo,hi}
//                  -> hi·hi + hi·lo + lo·hi  (triple, for the amplified path)
// MODE 1 (GEMM-2):  8 chunks, A sections {hi,lo}, B {hi,hi}
//                  -> (a_hi+a_lo)@w_hi      (exact activations x fp16 weights)
// 128x128 CTA tile, 8 warps, warp tile 64x32, m16n8k16; 3-stage cp.async
// pipeline, one __syncthreads per chunk.
// ===========================================================================
template <int MODE, int NSTORE, int LDC>
__global__ __launch_bounds__(256, 2)
void f16_gemm(const __half* __restrict__ A,
              const __half* __restrict__ BT,
              const float* __restrict__ bias,
              float* __restrict__ Cm) {
    extern __shared__ char dyn_raw[];
    const uint32_t raw = smem_u32(dyn_raw);
    const uint32_t sb  = (raw + 1023) & ~1023u;

    constexpr int NCH = (MODE == 0) ? 12 : 8;

    const int tid  = threadIdx.x;
    const int wid  = tid >> 5;
    const int lane = tid & 31;
    const int row0 = blockIdx.y * 128;
    const int col0 = blockIdx.x * 128;
    const int wm   = (wid >> 2) * 64;
    const int wn   = (wid & 3) * 32;

    float acc[4][4][4];
#pragma unroll
    for (int mi = 0; mi < 4; mi++)
#pragma unroll
        for (int ni = 0; ni < 4; ni++)
#pragma unroll
            for (int v = 0; v < 4; v++) acc[mi][ni][v] = 0.f;

    const int lrow = tid >> 3;          // 0..31 (x4 rows per iter)
    const int lblk = tid & 7;           // 16B chunk

    auto kA = [](int c) {
        if (MODE == 0) { const int s[3] = {0, 0, 256}; return s[c >> 2] + (c & 3) * 64; }
        else           { const int s[2] = {0, 256};    return s[c >> 2] + (c & 3) * 64; }
    };
    auto kB = [](int c) {
        if (MODE == 0) { const int s[3] = {0, 256, 0}; return s[c >> 2] + (c & 3) * 64; }
        else           { return (c & 3) * 64; }
    };

    auto load_stage = [&](int c, int st) {
        uint32_t a_t = sb + st * 32768;
        uint32_t b_t = a_t + 16384;
        const __half* ag = A  + (size_t)(row0 + lrow) * KS + kA(c) + lblk * 8;
        const __half* bg = BT + (size_t)(col0 + lrow) * KS + kB(c) + lblk * 8;
#pragma unroll
        for (int i = 0; i < 4; i++) {
            int r = lrow + i * 32;
            cp16(a_t + swz(r * 128 + lblk * 16), ag + (size_t)i * 32 * KS);
            cp16(b_t + swz(r * 128 + lblk * 16), bg + (size_t)i * 32 * KS);
        }
        CP_COMMIT();
    };

    load_stage(0, 0);
    load_stage(1, 1);

    for (int c = 0; c < NCH; c++) {
        if (c + 1 < NCH) { CP_WAIT(1); } else { CP_WAIT(0); }
        __syncthreads();
        if (c + 2 < NCH) load_stage(c + 2, (c + 2) % 3);

        const uint32_t a_t = sb + (c % 3) * 32768;
        const uint32_t b_t = a_t + 16384;
#pragma unroll
        for (int ks = 0; ks < 4; ks++) {
            uint32_t af[4][4];
#pragma unroll
            for (int mi = 0; mi < 4; mi++) {
                int r  = wm + mi * 16 + (lane & 15);
                int kc = ks * 16 + (lane >> 4) * 8;
                ldsm4(af[mi], a_t + swz(r * 128 + kc * 2));
            }
            uint32_t bf[4][2];
#pragma unroll
            for (int nj = 0; nj < 2; nj++) {
                int gsel = lane >> 3;
                int nrow = wn + (nj * 2 + (gsel >> 1)) * 8 + (lane & 7);
                int kc   = ks * 16 + (gsel & 1) * 8;
                uint32_t r4[4];
                ldsm4(r4, b_t + swz(nrow * 128 + kc * 2));
                bf[nj * 2][0]     = r4[0];
                bf[nj * 2][1]     = r4[1];
                bf[nj * 2 + 1][0] = r4[2];
                bf[nj * 2 + 1][1] = r4[3];
            }
#pragma unroll
            for (int mi = 0; mi < 4; mi++)
#pragma unroll
                for (int ni = 0; ni < 4; ni++)
                    mma_f16(acc[mi][ni], af[mi], bf[ni]);
        }
    }

    // ---- epilogue ----
    const int r = lane >> 2;
    const int q = lane & 3;
#pragma unroll
    for (int mi = 0; mi < 4; mi++) {
#pragma unroll
        for (int ni = 0; ni < 4; ni++) {
            int row = row0 + wm + mi * 16 + r;
            int c   = col0 + wn + ni * 8 + 2 * q;
            if (c < NSTORE) {
                float b0 = bias[c], b1 = bias[c + 1];
                float2 v0 = make_float2(acc[mi][ni][0] + b0, acc[mi][ni][1] + b1);
                float2 v1 = make_float2(acc[mi][ni][2] + b0, acc[mi][ni][3] + b1);
                *(float2*)&Cm[(size_t)row * LDC + c]       = v0;
                *(float2*)&Cm[(size_t)(row + 8) * LDC + c] = v1;
            }
        }
    }
}

// ---------------------------------------------------------------------------
// Sampling v4: 8-LANE group <-> (b, n, head) — 4 items per warp.
// Within 8 lanes: corner g=(lane>>1)&3, lane handles 16 channels
// (2 x uint4; 2 lanes = full 64B corner row). Compute/load/fma phases
// (MLP=8 gathers in flight). 2-round bfly (xor 2, 4). Lanes g==0
// ((lane&7)<2) write the fp16 split of agg (2+2 uint4 stores).
// ---------------------------------------------------------------------------
__global__ void sample_kernel(const float* __restrict__ refp) {
    int tid  = blockIdx.x * blockDim.x + threadIdx.x;
    int lane = threadIdx.x & 31;
    int it   = tid >> 3;                  // global item = (b*N + n)*8 + h
    int h    = it & 7;
    int bn   = it >> 3;
    int b    = bn >> 13;

    int g   = (lane >> 1) & 3;            // bilinear corner
    int gx  = g & 1, gy = g >> 1;
    int d16 = (lane & 1) * 16;            // halves offset (16 channels/lane)

    const float* pr = g_params + (size_t)bn * P96;

    float bx = 2.f * refp[2 * bn];
    float by = 2.f * refp[2 * bn + 1];

    const float* al = pr + 64 + h * 4;
    float l0 = al[0], l1 = al[1], l2 = al[2], l3 = al[3];
    float mx = fmaxf(fmaxf(l0, l1), fmaxf(l2, l3));
    float e0 = __expf(l0 - mx), e1 = __expf(l1 - mx);
    float e2 = __expf(l2 - mx), e3 = __expf(l3 - mx);
    float inv = 1.f / (e0 + e1 + e2 + e3);
    float aw[4] = {e0 * inv, e1 * inv, e2 * inv, e3 * inv};

    const __half* vb = g_valth + (size_t)(b * NH_ + h) * HW_ * 32;

    // phase 1: all 4 points' corner weights + indices
    float wcv[4];
    int   idxv[4];
#pragma unroll
    for (int p = 0; p < 4; p++) {
        float ox = pr[(h * 4 + p) * 2];
        float oy = pr[(h * 4 + p) * 2 + 1];
        float x = fmaf(bx + ox, (float)W_ * 0.5f, -0.5f);
        float y = fmaf(by + oy, (float)H_ * 0.5f, -0.5f);
        float x0f = floorf(x), y0f = floorf(y);
        float wx = x - x0f, wy = y - y0f;
        int xc = (int)x0f + gx;
        int yc = (int)y0f + gy;
        float wcx = gx ? wx : 1.f - wx;
        float wcy = gy ? wy : 1.f - wy;
        bool valid = (xc >= 0) & (xc < W_) & (yc >= 0) & (yc < H_);
        wcv[p]  = valid ? (wcx * wcy * aw[p]) : 0.f;
        idxv[p] = valid ? (yc * W_ + xc) : 0;
    }
    // phase 2: all 8 gathers in flight
    uint4 vv[4][2];
#pragma unroll
    for (int p = 0; p < 4; p++) {
        const __half* src = &vb[(size_t)idxv[p] * 32 + d16];
        vv[p][0] = *(const uint4*)(src);
        vv[p][1] = *(const uint4*)(src + 8);
    }
    // phase 3: convert + accumulate (16 channels per lane)
    float acc[16];
#pragma unroll
    for (int j = 0; j < 16; j++) acc[j] = 0.f;
#pragma unroll
    for (int p = 0; p < 4; p++) {
        float wc = wcv[p];
#pragma unroll
        for (int half = 0; half < 2; half++) {
            const uint32_t* u = &vv[p][half].x;
#pragma unroll
            for (int j = 0; j < 4; j++) {
                float2 f = __half22float2(*reinterpret_cast<const __half2*>(&u[j]));
                acc[half * 8 + 2 * j]     = fmaf(wc, f.x, acc[half * 8 + 2 * j]);
                acc[half * 8 + 2 * j + 1] = fmaf(wc, f.y, acc[half * 8 + 2 * j + 1]);
            }
        }
    }

    // reduce across corner groups (lanes l, l^2, l^4 within 8-lane item)
#pragma unroll
    for (int off = 2; off <= 4; off <<= 1)
#pragma unroll
        for (int j = 0; j < 16; j++)
            acc[j] += __shfl_xor_sync(0xffffffffu, acc[j], off);

    if (g == 0) {
        __half hh[16], ll[16];
#pragma unroll
        for (int j = 0; j < 16; j++) split2h(acc[j], hh[j], ll[j]);
        __half* base = g_as + (size_t)bn * KS + h * 32 + d16;
        uint4 uh[2], ul[2];
#pragma unroll
        for (int half = 0; half < 2; half++) {
            uint32_t* ph = &uh[half].x;
            uint32_t* pl = &ul[half].x;
#pragma unroll
            for (int j = 0; j < 4; j++) {
                __half2 a(hh[half * 8 + 2 * j], hh[half * 8 + 2 * j + 1]);
                __half2 c(ll[half * 8 + 2 * j], ll[half * 8 + 2 * j + 1]);
                ph[j] = *reinterpret_cast<uint32_t*>(&a);
                pl[j] = *reinterpret_cast<uint32_t*>(&c);
            }
        }
        *(uint4*)(base)           = uh[0];
        *(uint4*)(base + 8)       = uh[1];
        *(uint4*)(base + 256)     = ul[0];
        *(uint4*)(base + 264)     = ul[1];
    }
}

// ---------------------------------------------------------------------------
extern "C" void kernel_launch(void* const* d_in, const int* in_sizes, int n_in,
                              void* d_out, int out_size) {
    const float* query  = (const float*)d_in[0];
    const float* refp   = (const float*)d_in[1];
    const float* value  = (const float*)d_in[2];
    const float* W_off  = (const float*)d_in[3];
    const float* b_off  = (const float*)d_in[4];
    const float* W_attn = (const float*)d_in[5];
    const float* b_attn = (const float*)d_in[6];
    const float* W_out  = (const float*)d_in[7];
    const float* b_out  = (const float*)d_in[8];
    float* out = (float*)d_out;

    __half *qs, *as, *wc, *wo;
    float *params, *bcat;
    cudaGetSymbolAddress((void**)&qs, g_qs);
    cudaGetSymbolAddress((void**)&as, g_as);
    cudaGetSymbolAddress((void**)&wc, g_wc);
    cudaGetSymbolAddress((void**)&wo, g_wo);
    cudaGetSymbolAddress((void**)&params, g_params);
    cudaGetSymbolAddress((void**)&bcat, g_bcat);

    const int SMEM = 3 * 32768 + 1024;   // 3-stage pipeline + align pad
    cudaFuncSetAttribute(f16_gemm<0, P96, P96>,
                         cudaFuncAttributeMaxDynamicSharedMemorySize, SMEM);
    cudaFuncSetAttribute(f16_gemm<1, C_, C_>,
                         cudaFuncAttributeMaxDynamicSharedMemorySize, SMEM);

    split_query_kernel<<<M_ * C_ / 4 / 256, 256>>>(query);
    prep_wcat_kernel<<<128 * C_ / 256, 256>>>(W_off, b_off, W_attn, b_attn);
    prep_wout_kernel<<<C_ * C_ / 256, 256>>>(W_out);
    transpose_val_kernel<<<dim3(HW_ / 64, B_ * NH_), 256>>>(value);

    // GEMM-1: params[M,96] = q_hi@w_hi + q_hi@w_lo + q_lo@w_hi + bcat
    f16_gemm<0, P96, P96><<<dim3(1, M_ / 128), 256, SMEM>>>(qs, wc, bcat, params);

    // 4 items per warp -> 32 items per 256-thread block
    sample_kernel<<<(B_ * N_ * NH_) / 32, 256>>>(refp);

    // GEMM-2: out[M,256] = (a_hi + a_lo) @ wo_hi + b_out
    f16_gemm<1, C_, C_><<<dim3(2, M_ / 128), 256, SMEM>>>(as, wo, b_out, out);
}

// round 13
// speedup vs baseline: 1.3065x; 1.3065x over previous
#include <cuda_runtime.h>
#include <cuda_fp16.h>
#include <math.h>
#include <stdint.h>

#define B_   8
#define N_   8192
#define C_   256
#define H_   128
#define W_   128
#define NH_  8
#define HW_  (H_ * W_)
#define M_   (B_ * N_)      // 65536
#define P96  96
#define KS   512            // stored K (hi | lo), both GEMMs

// ---- scratch (static device allocations; no cudaMalloc anywhere) ----
__device__ __half g_valth[(size_t)B_ * NH_ * HW_ * 32];     // (B,Hh,HW,D) fp16, 67MB
__device__ float g_params[(size_t)M_ * P96];                // [off(64) | attn(32)]
__device__ __half g_qs[(size_t)M_ * KS];                    // query splits [M][512]
__device__ __half g_as[(size_t)M_ * KS];                    // agg splits   [M][512]
__device__ __half g_wc[128 * KS];                           // wcat^T splits (pad rows 96-127)
__device__ __half g_wo[C_ * KS];                            // W_out^T splits
__device__ float g_bcat[P96];

// ============================ PTX helpers ==================================
__device__ __forceinline__ uint32_t smem_u32(const void* p) {
    uint32_t a;
    asm("{ .reg .u64 t; cvta.to.shared.u64 t, %1; cvt.u32.u64 %0, t; }"
        : "=r"(a) : "l"(p));
    return a;
}
__device__ __forceinline__ void cp16(uint32_t dst, const void* src) {
    asm volatile("cp.async.cg.shared.global [%0], [%1], 16;" :: "r"(dst), "l"(src));
}
#define CP_COMMIT() asm volatile("cp.async.commit_group;" ::: "memory")
#define CP_WAIT(n)  asm volatile("cp.async.wait_group %0;" :: "n"(n) : "memory")

__device__ __forceinline__ void ldsm4(uint32_t* r, uint32_t addr) {
    asm volatile("ldmatrix.sync.aligned.m8n8.x4.shared.b16 {%0,%1,%2,%3}, [%4];"
                 : "=r"(r[0]), "=r"(r[1]), "=r"(r[2]), "=r"(r[3]) : "r"(addr));
}
__device__ __forceinline__ void mma_f16(float* d, const uint32_t* a, const uint32_t* b) {
    asm volatile(
        "mma.sync.aligned.m16n8k16.row.col.f32.f16.f16.f32 "
        "{%0,%1,%2,%3}, {%4,%5,%6,%7}, {%8,%9}, {%0,%1,%2,%3};"
        : "+f"(d[0]), "+f"(d[1]), "+f"(d[2]), "+f"(d[3])
        : "r"(a[0]), "r"(a[1]), "r"(a[2]), "r"(a[3]), "r"(b[0]), "r"(b[1]));
}
__device__ __forceinline__ uint32_t swz(uint32_t off) { return off ^ ((off >> 3) & 0x70); }

// ============================ fp16 2-way split =============================
__device__ __forceinline__ void split2h(float v, __half& h, __half& l) {
    h = __float2half(v);
    l = __float2half(v - __half2float(h));
}

// query -> [M][512] (hi | lo)
__global__ void split_query_kernel(const float* __restrict__ q) {
    size_t i = (size_t)(blockIdx.x * blockDim.x + threadIdx.x) * 4;
    float4 v = *(const float4*)&q[i];
    size_t row = i >> 8;
    int col = (int)(i & 255);
    __half h[4], l[4];
    split2h(v.x, h[0], l[0]); split2h(v.y, h[1], l[1]);
    split2h(v.z, h[2], l[2]); split2h(v.w, h[3], l[3]);
    __half* base = g_qs + row * KS + col;
    *(__half2*)(base)       = __half2(h[0], h[1]);
    *(__half2*)(base + 2)   = __half2(h[2], h[3]);
    *(__half2*)(base + 256) = __half2(l[0], l[1]);
    *(__half2*)(base + 258) = __half2(l[2], l[3]);
}

// wcat^T -> [128][512] padded with zero rows 96..127
__global__ void prep_wcat_kernel(const float* __restrict__ W_off,
                                 const float* __restrict__ b_off,
                                 const float* __restrict__ W_attn,
                                 const float* __restrict__ b_attn) {
    int id = blockIdx.x * blockDim.x + threadIdx.x;   // 128*256
    int j = id >> 8, k = id & 255;
    float v = 0.f;
    if (j < 64)       v = W_off[k * 64 + j];
    else if (j < 96)  v = W_attn[k * 32 + (j - 64)];
    __half h, l;
    split2h(v, h, l);
    g_wc[j * KS + k] = h; g_wc[j * KS + 256 + k] = l;
    if (id < P96) g_bcat[id] = (id < 64) ? b_off[id] : b_attn[id - 64];
}

// W_out^T -> [256][512]
__global__ void prep_wout_kernel(const float* __restrict__ W_out) {
    int id = blockIdx.x * blockDim.x + threadIdx.x;   // 256*256
    int n = id >> 8, k = id & 255;
    __half h, l;
    split2h(W_out[k * C_ + n], h, l);
    g_wo[n * KS + k] = h; g_wo[n * KS + 256 + k] = l;
}

// ---------------------------------------------------------------------------
// Transpose v4: (B, Hh*D, H*W) fp32 -> (B, Hh, H*W, D) fp16.
// ---------------------------------------------------------------------------
__global__ void transpose_val_kernel(const float* __restrict__ val) {
    __shared__ float4 t4[64][8];
    int bh = blockIdx.y;
    int p0 = blockIdx.x * 64;
    int tid = threadIdx.x;
    int dl = tid >> 6;         // 0..3
    int pl = tid & 63;         // 0..63
    const float* src = val + ((size_t)bh * 32) * HW_ + p0 + pl;
#pragma unroll
    for (int i = 0; i < 2; i++) {
        int dq = dl * 2 + i;   // 0..7
        float4 v;
        v.x = src[(size_t)(dq * 4 + 0) * HW_];
        v.y = src[(size_t)(dq * 4 + 1) * HW_];
        v.z = src[(size_t)(dq * 4 + 2) * HW_];
        v.w = src[(size_t)(dq * 4 + 3) * HW_];
        t4[pl][dq ^ (pl & 7)] = v;
    }
    __syncthreads();
    int c  = tid & 7;          // output d-quad
    int pw = tid >> 3;         // 0..31
    __half* dst = g_valth + (size_t)bh * HW_ * 32 + (size_t)p0 * 32;
#pragma unroll
    for (int i = 0; i < 2; i++) {
        int p = pw + i * 32;
        float4 v = t4[p][c ^ (p & 7)];
        __half2 h01 = __floats2half2_rn(v.x, v.y);
        __half2 h23 = __floats2half2_rn(v.z, v.w);
        uint2 u;
        u.x = *reinterpret_cast<uint32_t*>(&h01);
        u.y = *reinterpret_cast<uint32_t*>(&h23);
        *(uint2*)&dst[(size_t)p * 32 + c * 4] = u;
    }
}

// ===========================================================================
// fp16 mma.sync GEMM, split-compensated.
// MODE 0 (GEMM-1): 12 chunks, A sections {hi,hi,lo}, B {hi,lo,hi}
//                  -> hi·hi + hi·lo + lo·hi  (triple, for the amplified path)
// MODE 1 (GEMM-2):  8 chunks, A sections {hi,lo}, B {hi,hi}
//                  -> (a_hi+a_lo)@w_hi      (exact activations x fp16 weights)
// 128x128 CTA tile, 8 warps, warp tile 64x32, m16n8k16; 3-stage cp.async
// pipeline, one __syncthreads per chunk.
// ===========================================================================
template <int MODE, int NSTORE, int LDC>
__global__ __launch_bounds__(256, 2)
void f16_gemm(const __half* __restrict__ A,
              const __half* __restrict__ BT,
              const float* __restrict__ bias,
              float* __restrict__ Cm) {
    extern __shared__ char dyn_raw[];
    const uint32_t raw = smem_u32(dyn_raw);
    const uint32_t sb  = (raw + 1023) & ~1023u;

    constexpr int NCH = (MODE == 0) ? 12 : 8;

    const int tid  = threadIdx.x;
    const int wid  = tid >> 5;
    const int lane = tid & 31;
    const int row0 = blockIdx.y * 128;
    const int col0 = blockIdx.x * 128;
    const int wm   = (wid >> 2) * 64;
    const int wn   = (wid & 3) * 32;

    float acc[4][4][4];
#pragma unroll
    for (int mi = 0; mi < 4; mi++)
#pragma unroll
        for (int ni = 0; ni < 4; ni++)
#pragma unroll
            for (int v = 0; v < 4; v++) acc[mi][ni][v] = 0.f;

    const int lrow = tid >> 3;          // 0..31 (x4 rows per iter)
    const int lblk = tid & 7;           // 16B chunk

    auto kA = [](int c) {
        if (MODE == 0) { const int s[3] = {0, 0, 256}; return s[c >> 2] + (c & 3) * 64; }
        else           { const int s[2] = {0, 256};    return s[c >> 2] + (c & 3) * 64; }
    };
    auto kB = [](int c) {
        if (MODE == 0) { const int s[3] = {0, 256, 0}; return s[c >> 2] + (c & 3) * 64; }
        else           { return (c & 3) * 64; }
    };

    auto load_stage = [&](int c, int st) {
        uint32_t a_t = sb + st * 32768;
        uint32_t b_t = a_t + 16384;
        const __half* ag = A  + (size_t)(row0 + lrow) * KS + kA(c) + lblk * 8;
        const __half* bg = BT + (size_t)(col0 + lrow) * KS + kB(c) + lblk * 8;
#pragma unroll
        for (int i = 0; i < 4; i++) {
            int r = lrow + i * 32;
            cp16(a_t + swz(r * 128 + lblk * 16), ag + (size_t)i * 32 * KS);
            cp16(b_t + swz(r * 128 + lblk * 16), bg + (size_t)i * 32 * KS);
        }
        CP_COMMIT();
    };

    load_stage(0, 0);
    load_stage(1, 1);

    for (int c = 0; c < NCH; c++) {
        if (c + 1 < NCH) { CP_WAIT(1); } else { CP_WAIT(0); }
        __syncthreads();
        if (c + 2 < NCH) load_stage(c + 2, (c + 2) % 3);

        const uint32_t a_t = sb + (c % 3) * 32768;
        const uint32_t b_t = a_t + 16384;
#pragma unroll
        for (int ks = 0; ks < 4; ks++) {
            uint32_t af[4][4];
#pragma unroll
            for (int mi = 0; mi < 4; mi++) {
                int r  = wm + mi * 16 + (lane & 15);
                int kc = ks * 16 + (lane >> 4) * 8;
                ldsm4(af[mi], a_t + swz(r * 128 + kc * 2));
            }
            uint32_t bf[4][2];
#pragma unroll
            for (int nj = 0; nj < 2; nj++) {
                int gsel = lane >> 3;
                int nrow = wn + (nj * 2 + (gsel >> 1)) * 8 + (lane & 7);
                int kc   = ks * 16 + (gsel & 1) * 8;
                uint32_t r4[4];
                ldsm4(r4, b_t + swz(nrow * 128 + kc * 2));
                bf[nj * 2][0]     = r4[0];
                bf[nj * 2][1]     = r4[1];
                bf[nj * 2 + 1][0] = r4[2];
                bf[nj * 2 + 1][1] = r4[3];
            }
#pragma unroll
            for (int mi = 0; mi < 4; mi++)
#pragma unroll
                for (int ni = 0; ni < 4; ni++)
                    mma_f16(acc[mi][ni], af[mi], bf[ni]);
        }
    }

    // ---- epilogue ----
    const int r = lane >> 2;
    const int q = lane & 3;
#pragma unroll
    for (int mi = 0; mi < 4; mi++) {
#pragma unroll
        for (int ni = 0; ni < 4; ni++) {
            int row = row0 + wm + mi * 16 + r;
            int c   = col0 + wn + ni * 8 + 2 * q;
            if (c < NSTORE) {
                float b0 = bias[c], b1 = bias[c + 1];
                float2 v0 = make_float2(acc[mi][ni][0] + b0, acc[mi][ni][1] + b1);
                float2 v1 = make_float2(acc[mi][ni][2] + b0, acc[mi][ni][3] + b1);
                *(float2*)&Cm[(size_t)row * LDC + c]       = v0;
                *(float2*)&Cm[(size_t)(row + 8) * LDC + c] = v1;
            }
        }
    }
}

// ---------------------------------------------------------------------------
// Sampling v3 (proven in R11): HALF-WARP <-> (b, n, head) — 2 items/warp.
// Within 16 lanes: corner g=(lane>>2)&3, lane loads uint4 = 8 halves
// (4 lanes x 16B = full 64B corner row). Compute/load/fma phases (MLP=4).
// 2-round bfly (xor 4, 8). Lanes g==0 write the fp16 split of agg.
// ---------------------------------------------------------------------------
__global__ void sample_kernel(const float* __restrict__ refp) {
    int gw   = (blockIdx.x * blockDim.x + threadIdx.x) >> 5;
    int lane = threadIdx.x & 31;
    int sub  = lane >> 4;                 // item within warp
    int it   = gw * 2 + sub;              // (b*N + n)*8 + h
    int h    = it & 7;
    int bn   = it >> 3;
    int b    = bn >> 13;

    int g  = (lane >> 2) & 3;             // bilinear corner
    int gx = g & 1, gy = g >> 1;
    int d8 = (lane & 3) * 8;              // halves offset

    const float* pr = g_params + (size_t)bn * P96;

    float bx = 2.f * refp[2 * bn];
    float by = 2.f * refp[2 * bn + 1];

    const float* al = pr + 64 + h * 4;
    float l0 = al[0], l1 = al[1], l2 = al[2], l3 = al[3];
    float mx = fmaxf(fmaxf(l0, l1), fmaxf(l2, l3));
    float e0 = __expf(l0 - mx), e1 = __expf(l1 - mx);
    float e2 = __expf(l2 - mx), e3 = __expf(l3 - mx);
    float inv = 1.f / (e0 + e1 + e2 + e3);
    float aw[4] = {e0 * inv, e1 * inv, e2 * inv, e3 * inv};

    const __half* vb = g_valth + (size_t)(b * NH_ + h) * HW_ * 32;

    // phase 1: all 4 points' corner weights + indices
    float wcv[4];
    int   idxv[4];
#pragma unroll
    for (int p = 0; p < 4; p++) {
        float ox = pr[(h * 4 + p) * 2];
        float oy = pr[(h * 4 + p) * 2 + 1];
        float x = fmaf(bx + ox, (float)W_ * 0.5f, -0.5f);
        float y = fmaf(by + oy, (float)H_ * 0.5f, -0.5f);
        float x0f = floorf(x), y0f = floorf(y);
        float wx = x - x0f, wy = y - y0f;
        int xc = (int)x0f + gx;
        int yc = (int)y0f + gy;
        float wcx = gx ? wx : 1.f - wx;
        float wcy = gy ? wy : 1.f - wy;
        bool valid = (xc >= 0) & (xc < W_) & (yc >= 0) & (yc < H_);
        wcv[p]  = valid ? (wcx * wcy * aw[p]) : 0.f;
        idxv[p] = valid ? (yc * W_ + xc) : 0;
    }
    // phase 2: all 4 gathers in flight
    uint4 vv[4];
#pragma unroll
    for (int p = 0; p < 4; p++)
        vv[p] = *(const uint4*)&vb[(size_t)idxv[p] * 32 + d8];
    // phase 3: convert + accumulate (8 channels per lane)
    float acc[8];
#pragma unroll
    for (int j = 0; j < 8; j++) acc[j] = 0.f;
#pragma unroll
    for (int p = 0; p < 4; p++) {
        float wc = wcv[p];
        const uint32_t* u = &vv[p].x;
#pragma unroll
        for (int j = 0; j < 4; j++) {
            float2 f = __half22float2(*reinterpret_cast<const __half2*>(&u[j]));
            acc[2 * j]     = fmaf(wc, f.x, acc[2 * j]);
            acc[2 * j + 1] = fmaf(wc, f.y, acc[2 * j + 1]);
        }
    }

    // reduce across corner groups (lanes l, l^4, l^8 within 16-lane item)
#pragma unroll
    for (int off = 4; off <= 8; off <<= 1)
#pragma unroll
        for (int j = 0; j < 8; j++)
            acc[j] += __shfl_xor_sync(0xffffffffu, acc[j], off);

    if (g == 0) {
        __half hh[8], ll[8];
#pragma unroll
        for (int j = 0; j < 8; j++) split2h(acc[j], hh[j], ll[j]);
        __half* base = g_as + (size_t)bn * KS + h * 32 + d8;
        uint4 uh, ul;
        uint32_t* ph = &uh.x;
        uint32_t* pl = &ul.x;
#pragma unroll
        for (int j = 0; j < 4; j++) {
            __half2 a(hh[2 * j], hh[2 * j + 1]);
            __half2 c(ll[2 * j], ll[2 * j + 1]);
            ph[j] = *reinterpret_cast<uint32_t*>(&a);
            pl[j] = *reinterpret_cast<uint32_t*>(&c);
        }
        *(uint4*)(base)       = uh;
        *(uint4*)(base + 256) = ul;
    }
}

// ---------------------------------------------------------------------------
extern "C" void kernel_launch(void* const* d_in, const int* in_sizes, int n_in,
                              void* d_out, int out_size) {
    const float* query  = (const float*)d_in[0];
    const float* refp   = (const float*)d_in[1];
    const float* value  = (const float*)d_in[2];
    const float* W_off  = (const float*)d_in[3];
    const float* b_off  = (const float*)d_in[4];
    const float* W_attn = (const float*)d_in[5];
    const float* b_attn = (const float*)d_in[6];
    const float* W_out  = (const float*)d_in[7];
    const float* b_out  = (const float*)d_in[8];
    float* out = (float*)d_out;

    __half *qs, *as, *wc, *wo;
    float *params, *bcat;
    cudaGetSymbolAddress((void**)&qs, g_qs);
    cudaGetSymbolAddress((void**)&as, g_as);
    cudaGetSymbolAddress((void**)&wc, g_wc);
    cudaGetSymbolAddress((void**)&wo, g_wo);
    cudaGetSymbolAddress((void**)&params, g_params);
    cudaGetSymbolAddress((void**)&bcat, g_bcat);

    const int SMEM = 3 * 32768 + 1024;   // 3-stage pipeline + align pad
    cudaFuncSetAttribute(f16_gemm<0, P96, P96>,
                         cudaFuncAttributeMaxDynamicSharedMemorySize, SMEM);
    cudaFuncSetAttribute(f16_gemm<1, C_, C_>,
                         cudaFuncAttributeMaxDynamicSharedMemorySize, SMEM);

    split_query_kernel<<<M_ * C_ / 4 / 256, 256>>>(query);
    prep_wcat_kernel<<<128 * C_ / 256, 256>>>(W_off, b_off, W_attn, b_attn);
    prep_wout_kernel<<<C_ * C_ / 256, 256>>>(W_out);
    transpose_val_kernel<<<dim3(HW_ / 64, B_ * NH_), 256>>>(value);

    // GEMM-1: params[M,96] = q_hi@w_hi + q_hi@w_lo + q_lo@w_hi + bcat
    f16_gemm<0, P96, P96><<<dim3(1, M_ / 128), 256, SMEM>>>(qs, wc, bcat, params);

    // 2 items per warp -> 16 items per 256-thread block (proven R11 config)
    sample_kernel<<<(B_ * N_ * NH_) / 16, 256>>>(refp);

    // GEMM-2: out[M,256] = (a_hi + a_lo) @ wo_hi + b_out
    f16_gemm<1, C_, C_><<<dim3(2, M_ / 128), 256, SMEM>>>(as, wo, b_out, out);
}

// round 14
// speedup vs baseline: 1.3504x; 1.0336x over previous
#include <cuda_runtime.h>
#include <cuda_fp16.h>
#include <math.h>
#include <stdint.h>

#define B_   8
#define N_   8192
#define C_   256
#define H_   128
#define W_   128
#define NH_  8
#define HW_  (H_ * W_)
#define M_   (B_ * N_)      // 65536
#define P96  96
#define KS   512            // stored K (hi | lo)

// ---- scratch (static device allocations; no cudaMalloc anywhere) ----
__device__ __half g_valth[(size_t)B_ * NH_ * HW_ * 32];     // (B,Hh,HW,D) fp16, 67MB
__device__ float g_params[(size_t)M_ * P96];                // [off(64) | attn(32)]
__device__ __half g_as[(size_t)M_ * KS];                    // agg splits [M][512]
__device__ __half g_wc[128 * KS];                           // wcat^T splits (pad rows 96-127)
__device__ __half g_wo[C_ * KS];                            // W_out^T splits
__device__ float g_bcat[P96];

// ============================ PTX helpers ==================================
__device__ __forceinline__ uint32_t smem_u32(const void* p) {
    uint32_t a;
    asm("{ .reg .u64 t; cvta.to.shared.u64 t, %1; cvt.u32.u64 %0, t; }"
        : "=r"(a) : "l"(p));
    return a;
}
__device__ __forceinline__ void cp16(uint32_t dst, const void* src) {
    asm volatile("cp.async.cg.shared.global [%0], [%1], 16;" :: "r"(dst), "l"(src));
}
#define CP_COMMIT() asm volatile("cp.async.commit_group;" ::: "memory")
#define CP_WAIT(n)  asm volatile("cp.async.wait_group %0;" :: "n"(n) : "memory")

__device__ __forceinline__ void ldsm4(uint32_t* r, uint32_t addr) {
    asm volatile("ldmatrix.sync.aligned.m8n8.x4.shared.b16 {%0,%1,%2,%3}, [%4];"
                 : "=r"(r[0]), "=r"(r[1]), "=r"(r[2]), "=r"(r[3]) : "r"(addr));
}
__device__ __forceinline__ void mma_f16(float* d, const uint32_t* a, const uint32_t* b) {
    asm volatile(
        "mma.sync.aligned.m16n8k16.row.col.f32.f16.f16.f32 "
        "{%0,%1,%2,%3}, {%4,%5,%6,%7}, {%8,%9}, {%0,%1,%2,%3};"
        : "+f"(d[0]), "+f"(d[1]), "+f"(d[2]), "+f"(d[3])
        : "r"(a[0]), "r"(a[1]), "r"(a[2]), "r"(a[3]), "r"(b[0]), "r"(b[1]));
}
#define STS128(addr, v) \
    asm volatile("st.shared.v4.b32 [%0], {%1,%2,%3,%4};" \
                 :: "r"(addr), "r"((v).x), "r"((v).y), "r"((v).z), "r"((v).w) : "memory")

__device__ __forceinline__ uint32_t swz(uint32_t off) { return off ^ ((off >> 3) & 0x70); }

// ============================ fp16 2-way split =============================
__device__ __forceinline__ void split2h(float v, __half& h, __half& l) {
    h = __float2half(v);
    l = __float2half(v - __half2float(h));
}

// ---------------------------------------------------------------------------
// Combined weight prep: wcat^T -> g_wc [128][512] (+bcat), W_out^T -> g_wo.
// ---------------------------------------------------------------------------
__global__ void prep_weights_kernel(const float* __restrict__ W_off,
                                    const float* __restrict__ b_off,
                                    const float* __restrict__ W_attn,
                                    const float* __restrict__ b_attn,
                                    const float* __restrict__ W_out) {
    int id = blockIdx.x * blockDim.x + threadIdx.x;
    if (id < 128 * 256) {
        int j = id >> 8, k = id & 255;
        float v = 0.f;
        if (j < 64)       v = W_off[k * 64 + j];
        else if (j < 96)  v = W_attn[k * 32 + (j - 64)];
        __half h, l;
        split2h(v, h, l);
        g_wc[j * KS + k] = h; g_wc[j * KS + 256 + k] = l;
        if (id < P96) g_bcat[id] = (id < 64) ? b_off[id] : b_attn[id - 64];
    } else {
        int id2 = id - 128 * 256;       // over 256*256
        int n = id2 >> 8, k = id2 & 255;
        __half h, l;
        split2h(W_out[k * C_ + n], h, l);
        g_wo[n * KS + k] = h; g_wo[n * KS + 256 + k] = l;
    }
}

// ---------------------------------------------------------------------------
// Transpose v4: (B, Hh*D, H*W) fp32 -> (B, Hh, H*W, D) fp16.
// ---------------------------------------------------------------------------
__global__ void transpose_val_kernel(const float* __restrict__ val) {
    __shared__ float4 t4[64][8];
    int bh = blockIdx.y;
    int p0 = blockIdx.x * 64;
    int tid = threadIdx.x;
    int dl = tid >> 6;         // 0..3
    int pl = tid & 63;         // 0..63
    const float* src = val + ((size_t)bh * 32) * HW_ + p0 + pl;
#pragma unroll
    for (int i = 0; i < 2; i++) {
        int dq = dl * 2 + i;   // 0..7
        float4 v;
        v.x = src[(size_t)(dq * 4 + 0) * HW_];
        v.y = src[(size_t)(dq * 4 + 1) * HW_];
        v.z = src[(size_t)(dq * 4 + 2) * HW_];
        v.w = src[(size_t)(dq * 4 + 3) * HW_];
        t4[pl][dq ^ (pl & 7)] = v;
    }
    __syncthreads();
    int c  = tid & 7;          // output d-quad
    int pw = tid >> 3;         // 0..31
    __half* dst = g_valth + (size_t)bh * HW_ * 32 + (size_t)p0 * 32;
#pragma unroll
    for (int i = 0; i < 2; i++) {
        int p = pw + i * 32;
        float4 v = t4[p][c ^ (p & 7)];
        __half2 h01 = __floats2half2_rn(v.x, v.y);
        __half2 h23 = __floats2half2_rn(v.z, v.w);
        uint2 u;
        u.x = *reinterpret_cast<uint32_t*>(&h01);
        u.y = *reinterpret_cast<uint32_t*>(&h23);
        *(uint2*)&dst[(size_t)p * 32 + c * 4] = u;
    }
}

// ===========================================================================
// GEMM-1 FUSED: params[M,96] = q_hi@w_hi + q_hi@w_lo + q_lo@w_hi + bcat.
// Reads fp32 query DIRECTLY (no split prepass): per 64-col fp32 chunk,
// LDG.128 -> split2h in regs -> STS swizzled A_hi/A_lo fp16 tiles, then
// 3 mma passes vs cp.async double-buffered weight tiles (w_hi, w_lo).
// 128x128 CTA tile (N=96 padded), 8 warps, warp tile 64x32, m16n8k16.
// ===========================================================================
__global__ __launch_bounds__(256)
void g1_fused_kernel(const float* __restrict__ Q,
                     const __half* __restrict__ WC,
                     const float* __restrict__ bias,
                     float* __restrict__ Cm) {
    extern __shared__ char dyn_raw[];
    const uint32_t raw = smem_u32(dyn_raw);
    const uint32_t sb  = (raw + 1023) & ~1023u;
    const uint32_t A_hi = sb;
    const uint32_t A_lo = sb + 16384;
    const uint32_t Bb   = sb + 32768;    // [st][whi|wlo] 16KB each

    const int tid  = threadIdx.x;
    const int wid  = tid >> 5;
    const int lane = tid & 31;
    const int row0 = blockIdx.y * 128;
    const int wm   = (wid >> 2) * 64;
    const int wn   = (wid & 3) * 32;

    float acc[4][4][4];
#pragma unroll
    for (int mi = 0; mi < 4; mi++)
#pragma unroll
        for (int ni = 0; ni < 4; ni++)
#pragma unroll
            for (int v = 0; v < 4; v++) acc[mi][ni][v] = 0.f;

    const int lrow = tid >> 3;          // 0..31
    const int lblk = tid & 7;           // 16B chunk

    auto loadB = [&](int c, int st) {
        uint32_t bh = Bb + st * 32768;
        uint32_t bl = bh + 16384;
        const __half* g1 = WC + (size_t)lrow * KS + c * 64 + lblk * 8;        // w_hi
        const __half* g2 = WC + (size_t)lrow * KS + 256 + c * 64 + lblk * 8;  // w_lo
#pragma unroll
        for (int i = 0; i < 4; i++) {
            int r = lrow + i * 32;
            cp16(bh + swz(r * 128 + lblk * 16), g1 + (size_t)i * 32 * KS);
            cp16(bl + swz(r * 128 + lblk * 16), g2 + (size_t)i * 32 * KS);
        }
        CP_COMMIT();
    };

    loadB(0, 0);
    loadB(1, 1);

    for (int c = 0; c < 4; c++) {
        __syncthreads();                 // previous compute done reading A tiles
        // build A_hi/A_lo fp16 tiles from fp32 query chunk c
#pragma unroll
        for (int v = tid; v < 1024; v += 256) {
            int r = v >> 3, blk = v & 7;
            const float* ap = Q + (size_t)(row0 + r) * 256 + c * 64 + blk * 8;
            float4 f0 = *(const float4*)(ap);
            float4 f1 = *(const float4*)(ap + 4);
            __half h[8], l[8];
            split2h(f0.x, h[0], l[0]); split2h(f0.y, h[1], l[1]);
            split2h(f0.z, h[2], l[2]); split2h(f0.w, h[3], l[3]);
            split2h(f1.x, h[4], l[4]); split2h(f1.y, h[5], l[5]);
            split2h(f1.z, h[6], l[6]); split2h(f1.w, h[7], l[7]);
            uint4 uh, ul;
            uint32_t* ph = &uh.x;
            uint32_t* pl = &ul.x;
#pragma unroll
            for (int j = 0; j < 4; j++) {
                __half2 a(h[2 * j], h[2 * j + 1]);
                __half2 b(l[2 * j], l[2 * j + 1]);
                ph[j] = *reinterpret_cast<uint32_t*>(&a);
                pl[j] = *reinterpret_cast<uint32_t*>(&b);
            }
            uint32_t so = swz(r * 128 + blk * 16);
            STS128(A_hi + so, uh);
            STS128(A_lo + so, ul);
        }
        if (c + 1 < 4) { loadB(c + 1, (c + 1) & 1); CP_WAIT(1); }
        else          { CP_WAIT(0); }
        __syncthreads();                 // A tiles + B(c) visible

        const uint32_t bhi = Bb + (c & 1) * 32768;
        const uint32_t blo = bhi + 16384;
        const uint32_t pa[3] = {A_hi, A_hi, A_lo};
        const uint32_t pb[3] = {bhi,  blo,  bhi};
#pragma unroll
        for (int pass = 0; pass < 3; pass++) {
            const uint32_t a_t = pa[pass];
            const uint32_t b_t = pb[pass];
#pragma unroll
            for (int ks = 0; ks < 4; ks++) {
                uint32_t af[4][4];
#pragma unroll
                for (int mi = 0; mi < 4; mi++) {
                    int r  = wm + mi * 16 + (lane & 15);
                    int kc = ks * 16 + (lane >> 4) * 8;
                    ldsm4(af[mi], a_t + swz(r * 128 + kc * 2));
                }
                uint32_t bf[4][2];
#pragma unroll
                for (int nj = 0; nj < 2; nj++) {
                    int gsel = lane >> 3;
                    int nrow = wn + (nj * 2 + (gsel >> 1)) * 8 + (lane & 7);
                    int kc   = ks * 16 + (gsel & 1) * 8;
                    uint32_t r4[4];
                    ldsm4(r4, b_t + swz(nrow * 128 + kc * 2));
                    bf[nj * 2][0]     = r4[0];
                    bf[nj * 2][1]     = r4[1];
                    bf[nj * 2 + 1][0] = r4[2];
                    bf[nj * 2 + 1][1] = r4[3];
                }
#pragma unroll
                for (int mi = 0; mi < 4; mi++)
#pragma unroll
                    for (int ni = 0; ni < 4; ni++)
                        mma_f16(acc[mi][ni], af[mi], bf[ni]);
            }
        }
    }

    // ---- epilogue ----
    const int r = lane >> 2;
    const int q = lane & 3;
#pragma unroll
    for (int mi = 0; mi < 4; mi++) {
#pragma unroll
        for (int ni = 0; ni < 4; ni++) {
            int row = row0 + wm + mi * 16 + r;
            int c   = wn + ni * 8 + 2 * q;
            if (c < P96) {
                float b0 = bias[c], b1 = bias[c + 1];
                float2 v0 = make_float2(acc[mi][ni][0] + b0, acc[mi][ni][1] + b1);
                float2 v1 = make_float2(acc[mi][ni][2] + b0, acc[mi][ni][3] + b1);
                *(float2*)&Cm[(size_t)row * P96 + c]       = v0;
                *(float2*)&Cm[(size_t)(row + 8) * P96 + c] = v1;
            }
        }
    }
}

// ===========================================================================
// GEMM-2: out[M,256] = (a_hi + a_lo) @ wo_hi + b_out.  8 chunks of K=64:
// A sections {hi,lo}, B section hi. 3-stage cp.async pipeline, one sync/chunk.
// ===========================================================================
__global__ __launch_bounds__(256, 2)
void f16_gemm2(const __half* __restrict__ A,
               const __half* __restrict__ BT,
               const float* __restrict__ bias,
               float* __restrict__ Cm) {
    extern __shared__ char dyn_raw[];
    const uint32_t raw = smem_u32(dyn_raw);
    const uint32_t sb  = (raw + 1023) & ~1023u;

    const int tid  = threadIdx.x;
    const int wid  = tid >> 5;
    const int lane = tid & 31;
    const int row0 = blockIdx.y * 128;
    const int col0 = blockIdx.x * 128;
    const int wm   = (wid >> 2) * 64;
    const int wn   = (wid & 3) * 32;

    float acc[4][4][4];
#pragma unroll
    for (int mi = 0; mi < 4; mi++)
#pragma unroll
        for (int ni = 0; ni < 4; ni++)
#pragma unroll
            for (int v = 0; v < 4; v++) acc[mi][ni][v] = 0.f;

    const int lrow = tid >> 3;
    const int lblk = tid & 7;

    auto kA = [](int c) { const int s[2] = {0, 256}; return s[c >> 2] + (c & 3) * 64; };
    auto kB = [](int c) { return (c & 3) * 64; };

    auto load_stage = [&](int c, int st) {
        uint32_t a_t = sb + st * 32768;
        uint32_t b_t = a_t + 16384;
        const __half* ag = A  + (size_t)(row0 + lrow) * KS + kA(c) + lblk * 8;
        const __half* bg = BT + (size_t)(col0 + lrow) * KS + kB(c) + lblk * 8;
#pragma unroll
        for (int i = 0; i < 4; i++) {
            int r = lrow + i * 32;
            cp16(a_t + swz(r * 128 + lblk * 16), ag + (size_t)i * 32 * KS);
            cp16(b_t + swz(r * 128 + lblk * 16), bg + (size_t)i * 32 * KS);
        }
        CP_COMMIT();
    };

    load_stage(0, 0);
    load_stage(1, 1);

    for (int c = 0; c < 8; c++) {
        if (c + 1 < 8) { CP_WAIT(1); } else { CP_WAIT(0); }
        __syncthreads();
        if (c + 2 < 8) load_stage(c + 2, (c + 2) % 3);

        const uint32_t a_t = sb + (c % 3) * 32768;
        const uint32_t b_t = a_t + 16384;
#pragma unroll
        for (int ks = 0; ks < 4; ks++) {
            uint32_t af[4][4];
#pragma unroll
            for (int mi = 0; mi < 4; mi++) {
                int r  = wm + mi * 16 + (lane & 15);
                int kc = ks * 16 + (lane >> 4) * 8;
                ldsm4(af[mi], a_t + swz(r * 128 + kc * 2));
            }
            uint32_t bf[4][2];
#pragma unroll
            for (int nj = 0; nj < 2; nj++) {
                int gsel = lane >> 3;
                int nrow = wn + (nj * 2 + (gsel >> 1)) * 8 + (lane & 7);
                int kc   = ks * 16 + (gsel & 1) * 8;
                uint32_t r4[4];
                ldsm4(r4, b_t + swz(nrow * 128 + kc * 2));
                bf[nj * 2][0]     = r4[0];
                bf[nj * 2][1]     = r4[1];
                bf[nj * 2 + 1][0] = r4[2];
                bf[nj * 2 + 1][1] = r4[3];
            }
#pragma unroll
            for (int mi = 0; mi < 4; mi++)
#pragma unroll
                for (int ni = 0; ni < 4; ni++)
                    mma_f16(acc[mi][ni], af[mi], bf[ni]);
        }
    }

    const int r = lane >> 2;
    const int q = lane & 3;
#pragma unroll
    for (int mi = 0; mi < 4; mi++) {
#pragma unroll
        for (int ni = 0; ni < 4; ni++) {
            int row = row0 + wm + mi * 16 + r;
            int c   = col0 + wn + ni * 8 + 2 * q;
            float b0 = bias[c], b1 = bias[c + 1];
            float2 v0 = make_float2(acc[mi][ni][0] + b0, acc[mi][ni][1] + b1);
            float2 v1 = make_float2(acc[mi][ni][2] + b0, acc[mi][ni][3] + b1);
            *(float2*)&Cm[(size_t)row * C_ + c]       = v0;
            *(float2*)&Cm[(size_t)(row + 8) * C_ + c] = v1;
        }
    }
}

// ---------------------------------------------------------------------------
// Sampling v3 (proven): HALF-WARP <-> (b, n, head) — 2 items/warp.
// ---------------------------------------------------------------------------
__global__ void sample_kernel(const float* __restrict__ refp) {
    int gw   = (blockIdx.x * blockDim.x + threadIdx.x) >> 5;
    int lane = threadIdx.x & 31;
    int sub  = lane >> 4;
    int it   = gw * 2 + sub;
    int h    = it & 7;
    int bn   = it >> 3;
    int b    = bn >> 13;

    int g  = (lane >> 2) & 3;
    int gx = g & 1, gy = g >> 1;
    int d8 = (lane & 3) * 8;

    const float* pr = g_params + (size_t)bn * P96;

    float bx = 2.f * refp[2 * bn];
    float by = 2.f * refp[2 * bn + 1];

    const float* al = pr + 64 + h * 4;
    float l0 = al[0], l1 = al[1], l2 = al[2], l3 = al[3];
    float mx = fmaxf(fmaxf(l0, l1), fmaxf(l2, l3));
    float e0 = __expf(l0 - mx), e1 = __expf(l1 - mx);
    float e2 = __expf(l2 - mx), e3 = __expf(l3 - mx);
    float inv = 1.f / (e0 + e1 + e2 + e3);
    float aw[4] = {e0 * inv, e1 * inv, e2 * inv, e3 * inv};

    const __half* vb = g_valth + (size_t)(b * NH_ + h) * HW_ * 32;

    float wcv[4];
    int   idxv[4];
#pragma unroll
    for (int p = 0; p < 4; p++) {
        float ox = pr[(h * 4 + p) * 2];
        float oy = pr[(h * 4 + p) * 2 + 1];
        float x = fmaf(bx + ox, (float)W_ * 0.5f, -0.5f);
        float y = fmaf(by + oy, (float)H_ * 0.5f, -0.5f);
        float x0f = floorf(x), y0f = floorf(y);
        float wx = x - x0f, wy = y - y0f;
        int xc = (int)x0f + gx;
        int yc = (int)y0f + gy;
        float wcx = gx ? wx : 1.f - wx;
        float wcy = gy ? wy : 1.f - wy;
        bool valid = (xc >= 0) & (xc < W_) & (yc >= 0) & (yc < H_);
        wcv[p]  = valid ? (wcx * wcy * aw[p]) : 0.f;
        idxv[p] = valid ? (yc * W_ + xc) : 0;
    }
    uint4 vv[4];
#pragma unroll
    for (int p = 0; p < 4; p++)
        vv[p] = *(const uint4*)&vb[(size_t)idxv[p] * 32 + d8];
    float acc[8];
#pragma unroll
    for (int j = 0; j < 8; j++) acc[j] = 0.f;
#pragma unroll
    for (int p = 0; p < 4; p++) {
        float wc = wcv[p];
        const uint32_t* u = &vv[p].x;
#pragma unroll
        for (int j = 0; j < 4; j++) {
            float2 f = __half22float2(*reinterpret_cast<const __half2*>(&u[j]));
            acc[2 * j]     = fmaf(wc, f.x, acc[2 * j]);
            acc[2 * j + 1] = fmaf(wc, f.y, acc[2 * j + 1]);
        }
    }

#pragma unroll
    for (int off = 4; off <= 8; off <<= 1)
#pragma unroll
        for (int j = 0; j < 8; j++)
            acc[j] += __shfl_xor_sync(0xffffffffu, acc[j], off);

    if (g == 0) {
        __half hh[8], ll[8];
#pragma unroll
        for (int j = 0; j < 8; j++) split2h(acc[j], hh[j], ll[j]);
        __half* base = g_as + (size_t)bn * KS + h * 32 + d8;
        uint4 uh, ul;
        uint32_t* ph = &uh.x;
        uint32_t* pl = &ul.x;
#pragma unroll
        for (int j = 0; j < 4; j++) {
            __half2 a(hh[2 * j], hh[2 * j + 1]);
            __half2 c(ll[2 * j], ll[2 * j + 1]);
            ph[j] = *reinterpret_cast<uint32_t*>(&a);
            pl[j] = *reinterpret_cast<uint32_t*>(&c);
        }
        *(uint4*)(base)       = uh;
        *(uint4*)(base + 256) = ul;
    }
}

// ---------------------------------------------------------------------------
extern "C" void kernel_launch(void* const* d_in, const int* in_sizes, int n_in,
                              void* d_out, int out_size) {
    const float* query  = (const float*)d_in[0];
    const float* refp   = (const float*)d_in[1];
    const float* value  = (const float*)d_in[2];
    const float* W_off  = (const float*)d_in[3];
    const float* b_off  = (const float*)d_in[4];
    const float* W_attn = (const float*)d_in[5];
    const float* b_attn = (const float*)d_in[6];
    const float* W_out  = (const float*)d_in[7];
    const float* b_out  = (const float*)d_in[8];
    float* out = (float*)d_out;

    __half *as, *wc, *wo;
    float *params, *bcat;
    cudaGetSymbolAddress((void**)&as, g_as);
    cudaGetSymbolAddress((void**)&wc, g_wc);
    cudaGetSymbolAddress((void**)&wo, g_wo);
    cudaGetSymbolAddress((void**)&params, g_params);
    cudaGetSymbolAddress((void**)&bcat, g_bcat);

    const int SMEM_G1 = 32768 + 65536 + 1024;   // A hi/lo + B 2-stage + pad
    const int SMEM_G2 = 3 * 32768 + 1024;       // 3-stage pipeline + pad
    cudaFuncSetAttribute(g1_fused_kernel,
                         cudaFuncAttributeMaxDynamicSharedMemorySize, SMEM_G1);
    cudaFuncSetAttribute(f16_gemm2,
                         cudaFuncAttributeMaxDynamicSharedMemorySize, SMEM_G2);

    prep_weights_kernel<<<(128 * 256 + 256 * 256) / 256, 256>>>(
        W_off, b_off, W_attn, b_attn, W_out);
    transpose_val_kernel<<<dim3(HW_ / 64, B_ * NH_), 256>>>(value);

    // GEMM-1 (fused split): params[M,96]
    g1_fused_kernel<<<dim3(1, M_ / 128), 256, SMEM_G1>>>(query, wc, bcat, params);

    // 2 items per warp -> 16 items per 256-thread block
    sample_kernel<<<(B_ * N_ * NH_) / 16, 256>>>(refp);

    // GEMM-2: out[M,256] = (a_hi + a_lo) @ wo_hi + b_out
    f16_gemm2<<<dim3(2, M_ / 128), 256, SMEM_G2>>>(as, wo, b_out, out);
}